// round 2
// baseline (speedup 1.0000x reference)
#include <cuda_runtime.h>
#include <math.h>

#define Bsz    4
#define Cseq   1024
#define TOK    4096
#define INDIM  128
#define DMODEL 256
#define DINNER 512
#define DSTATE 16
#define EPSV   1e-5f

#define EP_NONE     0
#define EP_BIAS     1
#define EP_SILU     2
#define EP_SOFTPLUS 3

// ---------------- scratch (static device allocation; no cudaMalloc) ----------------
#define OFF_XN   0u
#define OFF_SSM  524288u
#define OFF_WG   1572864u
#define OFF_U    2621440u     // 2 x 1048576
#define OFF_XZ   4718592u     // 2 x 4194304
#define OFF_XX   13107200u    // 2 x 2097152
#define OFF_DBL  17301504u    // 2 x 196608
#define OFF_DTP  17694720u    // 2 x 2097152
#define OFF_G    21889024u    // 2 x 2097152
#define OFF_MO   26083328u    // 2 x 1048576
#define OFF_RES  28180480u    // 2 x 1048576
#define OFF_COMB 30277632u
#define SCRATCH_FLOATS 31326208u

__device__ float g_scratch[SCRATCH_FLOATS];

// ---------------- rmsnorm (optionally + add) ----------------
template<int DIM, bool ADD>
__global__ void rmsnorm_kernel(const float* __restrict__ x, const float* __restrict__ w,
                               const float* __restrict__ add, float* __restrict__ out)
{
    const int t = blockIdx.x;
    const int i = threadIdx.x;
    float v = x[(size_t)t * DIM + i];
    float s = v * v;
    #pragma unroll
    for (int o = 16; o > 0; o >>= 1) s += __shfl_xor_sync(0xffffffffu, s, o);
    __shared__ float ws[DIM / 32];
    if ((i & 31) == 0) ws[i >> 5] = s;
    __syncthreads();
    float tot = 0.f;
    #pragma unroll
    for (int q = 0; q < DIM / 32; q++) tot += ws[q];
    float sc = rsqrtf(tot / (float)DIM + EPSV);
    float r = v * sc * w[i];
    if (ADD) r += add[(size_t)t * DIM + i];
    out[(size_t)t * DIM + i] = r;
}

// ---------------- generic SGEMM: C[M,N] = A[M,K(lda)] @ W[N,K]^T (+bias/act/resid) ----
// BM=64, BN=64, BK=16, 128 threads, per-thread 8x4
__global__ void sgemm_kernel(const float* __restrict__ A, const float* __restrict__ W,
                             const float* __restrict__ bias, const float* __restrict__ resid,
                             float* __restrict__ Cout,
                             int N, int K, int lda, int epil, int rev)
{
    __shared__ float As[16][65];
    __shared__ float Bs[16][65];
    const int tid = threadIdx.x;
    const int rowBase = blockIdx.y * 64;
    const int colBase = blockIdx.x * 64;
    const int tr = tid >> 4;   // 0..7
    const int tc = tid & 15;   // 0..15

    float acc[8][4];
    #pragma unroll
    for (int i = 0; i < 8; i++)
        #pragma unroll
        for (int j = 0; j < 4; j++) acc[i][j] = 0.f;

    for (int k0 = 0; k0 < K; k0 += 16) {
        #pragma unroll
        for (int i = 0; i < 8; i++) {
            int l = tid + i * 128;
            int m = l >> 4, k = l & 15;
            int row = rowBase + m;
            int srow = rev ? ((row & ~(Cseq - 1)) | (Cseq - 1 - (row & (Cseq - 1)))) : row;
            As[k][m] = A[(size_t)srow * lda + k0 + k];
        }
        #pragma unroll
        for (int i = 0; i < 8; i++) {
            int l = tid + i * 128;
            int n = l >> 4, k = l & 15;
            int col = colBase + n;
            Bs[k][n] = (col < N) ? W[(size_t)col * K + k0 + k] : 0.f;
        }
        __syncthreads();
        #pragma unroll
        for (int k = 0; k < 16; k++) {
            float a[8], bb[4];
            #pragma unroll
            for (int i = 0; i < 8; i++) a[i] = As[k][tr * 8 + i];
            #pragma unroll
            for (int j = 0; j < 4; j++) bb[j] = Bs[k][tc * 4 + j];
            #pragma unroll
            for (int i = 0; i < 8; i++)
                #pragma unroll
                for (int j = 0; j < 4; j++)
                    acc[i][j] = fmaf(a[i], bb[j], acc[i][j]);
        }
        __syncthreads();
    }

    #pragma unroll
    for (int i = 0; i < 8; i++) {
        int row = rowBase + tr * 8 + i;
        #pragma unroll
        for (int j = 0; j < 4; j++) {
            int col = colBase + tc * 4 + j;
            if (col < N) {
                float v = acc[i][j];
                if (epil != EP_NONE) v += bias[col];
                if (epil == EP_SILU) v = v / (1.f + __expf(-v));
                else if (epil == EP_SOFTPLUS) v = (v > 20.f) ? v : log1pf(__expf(v));
                if (resid) v += resid[(size_t)row * N + col];
                Cout[(size_t)row * N + col] = v;
            }
        }
    }
}

// ---------------- depthwise causal conv (K=4) + bias + silu ----------------
__global__ void conv_silu_kernel(const float* __restrict__ xz, const float* __restrict__ cw,
                                 const float* __restrict__ cb, float* __restrict__ out)
{
    int gid = blockIdx.x * blockDim.x + threadIdx.x;   // TOK*DINNER
    int d = gid & (DINNER - 1);
    int tok = gid >> 9;
    int c = tok & (Cseq - 1);
    float w0 = cw[d * 4 + 0], w1 = cw[d * 4 + 1], w2 = cw[d * 4 + 2], w3 = cw[d * 4 + 3];
    const float* base = xz + (size_t)tok * 1024 + d;   // xx = first half of xz row
    float v = cb[d] + w3 * base[0];
    if (c >= 1) v += w2 * base[-1024];
    if (c >= 2) v += w1 * base[-2048];
    if (c >= 3) v += w0 * base[-3072];
    out[gid] = v / (1.f + __expf(-v));
}

// ---------------- selective scan (fused z-gating) ----------------
// block = 128 threads = 32 channels x 4 state-quads; grid = (16 d-chunks, 4 batches)
__global__ void scan_kernel(const float* __restrict__ dtp, const float* __restrict__ xx,
                            const float* __restrict__ xz, const float* __restrict__ dbl,
                            const float* __restrict__ A_log, const float* __restrict__ Dp,
                            float* __restrict__ g)
{
    const int b   = blockIdx.y;
    const int tid = threadIdx.x;
    const int dl  = tid >> 2;         // 0..31
    const int q   = tid & 3;          // state quad
    const int d   = blockIdx.x * 32 + dl;

    float Areg[4], h[4];
    #pragma unroll
    for (int n = 0; n < 4; n++) {
        Areg[n] = -expf(A_log[d * 16 + q * 4 + n]);
        h[n] = 0.f;
    }
    const float Dv = Dp[d];

    __shared__ float sBC[32][32];     // [tt][0..15 = Bm, 16..31 = Cm]

    for (int t0 = 0; t0 < Cseq; t0 += 32) {
        __syncthreads();
        #pragma unroll
        for (int i = 0; i < 8; i++) {
            int l = tid + i * 128;
            int tt = l >> 5, j = l & 31;
            sBC[tt][j] = dbl[(size_t)(b * Cseq + t0 + tt) * 48 + 16 + j];
        }
        __syncthreads();
        for (int tt = 0; tt < 32; tt++) {
            size_t tok = (size_t)b * Cseq + t0 + tt;
            float dt = dtp[tok * DINNER + d];
            float xv = xx[tok * DINNER + d];
            float dx = dt * xv;
            float y = 0.f;
            #pragma unroll
            for (int n = 0; n < 4; n++) {
                float dA = __expf(dt * Areg[n]);
                h[n] = fmaf(dA, h[n], dx * sBC[tt][q * 4 + n]);
                y = fmaf(h[n], sBC[tt][16 + q * 4 + n], y);
            }
            y += __shfl_xor_sync(0xffffffffu, y, 1);
            y += __shfl_xor_sync(0xffffffffu, y, 2);
            if (q == 0) {
                float zv = xz[tok * 1024 + 512 + d];
                float yy = y + xv * Dv;
                g[tok * DINNER + d] = yy * (zv / (1.f + __expf(-zv)));
            }
        }
    }
}

// ---------------- gate combine: comb = w * (res_f + reverse_time(res_b)) ----------------
__global__ void combine_kernel(const float* __restrict__ wg, const float* __restrict__ rf,
                               const float* __restrict__ rb, float* __restrict__ out)
{
    int gid = blockIdx.x * blockDim.x + threadIdx.x;   // TOK*256
    int n = gid & 255;
    int tok = gid >> 8;
    int bq = tok >> 10, c = tok & 1023;
    int rtok = (bq << 10) | (1023 - c);
    out[gid] = wg[gid] * (rf[gid] + rb[((size_t)rtok << 8) + n]);
}

// ---------------- launch ----------------
extern "C" void kernel_launch(void* const* d_in, const int* in_sizes, int n_in,
                              void* d_out, int out_size)
{
    const float* x        = (const float*)d_in[0];
    const float* W_in     = (const float*)d_in[1];
    const float* b_in     = (const float*)d_in[2];
    const float* W_wp     = (const float*)d_in[3];
    const float* b_wp     = (const float*)d_in[4];
    const float* W_fp     = (const float*)d_in[5];
    const float* b_fp     = (const float*)d_in[6];
    const float* W_bp     = (const float*)d_in[7];
    const float* b_bp     = (const float*)d_in[8];
    const float* W_out    = (const float*)d_in[9];
    const float* b_out    = (const float*)d_in[10];
    const float* norm_top = (const float*)d_in[11];

    float* S = nullptr;
    cudaGetSymbolAddress((void**)&S, g_scratch);

    float* xn   = S + OFF_XN;
    float* ssm  = S + OFF_SSM;
    float* wg   = S + OFF_WG;
    float* u0   = S + OFF_U;
    float* u1   = S + OFF_U + 1048576u;
    float* res0 = S + OFF_RES;
    float* res1 = S + OFF_RES + 1048576u;
    float* comb = S + OFF_COMB;

    dim3 blk(128);

    // top rmsnorm
    rmsnorm_kernel<128, false><<<TOK, 128>>>(x, norm_top, nullptr, xn);
    // ssm_in = xn @ W_in^T + b_in ; wgate = silu(xn @ W_wp^T + b_wp)
    sgemm_kernel<<<dim3(4, 64), blk>>>(xn, W_in, b_in, nullptr, ssm, 256, 128, 128, EP_BIAS, 0);
    sgemm_kernel<<<dim3(4, 64), blk>>>(xn, W_wp, b_wp, nullptr, wg,  256, 128, 128, EP_SILU, 0);
    // fwd/bwd mamba inputs (bwd reads time-reversed rows)
    sgemm_kernel<<<dim3(4, 64), blk>>>(ssm, W_fp, b_fp, nullptr, u0, 256, 256, 256, EP_BIAS, 0);
    sgemm_kernel<<<dim3(4, 64), blk>>>(ssm, W_bp, b_bp, nullptr, u1, 256, 256, 256, EP_BIAS, 1);

    for (int dir = 0; dir < 2; dir++) {
        const float* in_w    = (const float*)d_in[12 + dir * 10 + 0];
        const float* conv_w  = (const float*)d_in[12 + dir * 10 + 1];
        const float* conv_b  = (const float*)d_in[12 + dir * 10 + 2];
        const float* xproj_w = (const float*)d_in[12 + dir * 10 + 3];
        const float* dt_w    = (const float*)d_in[12 + dir * 10 + 4];
        const float* dt_b    = (const float*)d_in[12 + dir * 10 + 5];
        const float* A_log   = (const float*)d_in[12 + dir * 10 + 6];
        const float* Dp      = (const float*)d_in[12 + dir * 10 + 7];
        const float* out_w   = (const float*)d_in[12 + dir * 10 + 8];
        const float* norm_w  = (const float*)d_in[12 + dir * 10 + 9];

        float* u    = (dir == 0) ? u0 : u1;
        float* res  = (dir == 0) ? res0 : res1;
        float* xzb  = S + OFF_XZ  + (size_t)dir * 4194304u;
        float* xxb  = S + OFF_XX  + (size_t)dir * 2097152u;
        float* dblb = S + OFF_DBL + (size_t)dir * 196608u;
        float* dtpb = S + OFF_DTP + (size_t)dir * 2097152u;
        float* gb   = S + OFF_G   + (size_t)dir * 2097152u;
        float* mob  = S + OFF_MO  + (size_t)dir * 1048576u;

        // xz = u @ in_w^T   (xx = cols [0,512), z = cols [512,1024))
        sgemm_kernel<<<dim3(16, 64), blk>>>(u, in_w, nullptr, nullptr, xzb, 1024, 256, 256, EP_NONE, 0);
        // depthwise causal conv4 + bias + silu
        conv_silu_kernel<<<(TOK * DINNER) / 256, 256>>>(xzb, conv_w, conv_b, xxb);
        // dbl = xx @ xproj_w^T  (dt|B|C, 48 cols)
        sgemm_kernel<<<dim3(1, 64), blk>>>(xxb, xproj_w, nullptr, nullptr, dblb, 48, 512, 512, EP_NONE, 0);
        // dtp = softplus(dbl[:, :16] @ dt_w^T + dt_b)
        sgemm_kernel<<<dim3(8, 64), blk>>>(dblb, dt_w, dt_b, nullptr, dtpb, 512, 16, 48, EP_SOFTPLUS, 0);
        // selective scan + D skip + z-gate -> g
        scan_kernel<<<dim3(16, 4), 128>>>(dtpb, xxb, xzb, dblb, A_log, Dp, gb);
        // mamba out = g @ out_w^T
        sgemm_kernel<<<dim3(4, 64), blk>>>(gb, out_w, nullptr, nullptr, mob, 256, 512, 512, EP_NONE, 0);
        // postnorm: rmsnorm(mo)*norm_w + u
        rmsnorm_kernel<256, true><<<TOK, 256>>>(mob, norm_w, u, res);
    }

    // comb = wgate * (res_f + time-reversed res_b)
    combine_kernel<<<(TOK * 256) / 256, 256>>>(wg, res0, res1, comb);
    // out = comb @ W_out^T + b_out + x   (residual)
    sgemm_kernel<<<dim3(2, 64), blk>>>(comb, W_out, b_out, x, (float*)d_out, 128, 256, 256, EP_BIAS, 0);
}

// round 3
// speedup vs baseline: 3.0933x; 3.0933x over previous
#include <cuda_runtime.h>
#include <math.h>

#define Bsz    4
#define Cseq   1024
#define TOK    4096
#define INDIM  128
#define DMODEL 256
#define DINNER 512
#define DSTATE 16
#define EPSV   1e-5f

#define EP_NONE 0
#define EP_BIAS 1
#define EP_SILU 2

// ---------------- scratch ----------------
#define OFF_XN   0u
#define OFF_SSM  524288u
#define OFF_WG   1572864u
#define OFF_U    2621440u     // 2 x 1048576
#define OFF_XZ   4718592u     // 2 x 4194304
#define OFF_XX   13107200u    // 2 x 2097152
#define OFF_DBL  17301504u    // 2 x 196608
#define OFF_G    17694720u    // 2 x 2097152
#define OFF_MO   21889024u    // 2 x 1048576
#define OFF_RES  23986176u    // 2 x 1048576
#define OFF_COMB 26083328u
#define SCRATCH_FLOATS 27131904u

__device__ float g_scratch[SCRATCH_FLOATS];

// ---------------- rmsnorm (top, DIM=128) ----------------
__global__ void rmsnorm128_kernel(const float* __restrict__ x, const float* __restrict__ w,
                                  float* __restrict__ out)
{
    const int t = blockIdx.x;
    const int i = threadIdx.x;
    float v = x[(size_t)t * 128 + i];
    float s = v * v;
    #pragma unroll
    for (int o = 16; o > 0; o >>= 1) s += __shfl_xor_sync(0xffffffffu, s, o);
    __shared__ float ws[4];
    if ((i & 31) == 0) ws[i >> 5] = s;
    __syncthreads();
    float tot = ws[0] + ws[1] + ws[2] + ws[3];
    float sc = rsqrtf(tot * (1.f / 128.f) + EPSV);
    out[(size_t)t * 128 + i] = v * sc * w[i];
}

// ---------------- postnorm pair (DIM=256, + add), blockIdx.y = dir ----------------
__global__ void rmsnorm_pair_kernel(const float* __restrict__ xb,
                                    const float* __restrict__ w0, const float* __restrict__ w1,
                                    const float* __restrict__ addb, float* __restrict__ outb)
{
    const int dir = blockIdx.y;
    const float* x   = xb   + (size_t)dir * 1048576u;
    const float* add = addb + (size_t)dir * 1048576u;
    float* out       = outb + (size_t)dir * 1048576u;
    const float* w   = dir ? w1 : w0;
    const int t = blockIdx.x;
    const int i = threadIdx.x;
    float v = x[(size_t)t * 256 + i];
    float s = v * v;
    #pragma unroll
    for (int o = 16; o > 0; o >>= 1) s += __shfl_xor_sync(0xffffffffu, s, o);
    __shared__ float ws[8];
    if ((i & 31) == 0) ws[i >> 5] = s;
    __syncthreads();
    float tot = 0.f;
    #pragma unroll
    for (int q = 0; q < 8; q++) tot += ws[q];
    float sc = rsqrtf(tot * (1.f / 256.f) + EPSV);
    out[(size_t)t * 256 + i] = v * sc * w[i] + add[(size_t)t * 256 + i];
}

// ---------------- SGEMM v2: 64x64 tile, BK=16, 256 thr, 4x4/thr, double-buffered ----
struct GP { const float* A; const float* W; const float* bias; const float* resid; float* C; };

__global__ void __launch_bounds__(256) sgemm2_kernel(GP g0, GP g1,
                                                     int N, int K, int lda,
                                                     int epil0, int epil1, int rev0, int rev1)
{
    const GP  p    = blockIdx.z ? g1 : g0;
    const int epil = blockIdx.z ? epil1 : epil0;
    const int rev  = blockIdx.z ? rev1 : rev0;

    __shared__ float As[2][16][68];
    __shared__ float Bs[2][16][68];

    const int tid = threadIdx.x;
    const int rowBase = blockIdx.y * 64;
    const int colBase = blockIdx.x * 64;
    const int am = tid >> 2;            // 0..63
    const int ak = (tid & 3) * 4;       // 0,4,8,12
    const int tr = tid >> 4;            // 0..15
    const int tc = tid & 15;            // 0..15

    int arow = rowBase + am;
    if (rev) arow ^= (Cseq - 1);        // per-batch time reversal (Cseq=1024 pow2)
    const float* Aptr = p.A + (size_t)arow * lda + ak;
    const int wcol = colBase + am;
    const bool wok = wcol < N;
    const float* Wptr = p.W + (size_t)(wok ? wcol : 0) * K + ak;

    // prologue: chunk 0
    float4 a0 = *(const float4*)Aptr;
    float4 b0 = wok ? *(const float4*)Wptr : make_float4(0.f, 0.f, 0.f, 0.f);
    As[0][ak + 0][am] = a0.x; As[0][ak + 1][am] = a0.y; As[0][ak + 2][am] = a0.z; As[0][ak + 3][am] = a0.w;
    Bs[0][ak + 0][am] = b0.x; Bs[0][ak + 1][am] = b0.y; Bs[0][ak + 2][am] = b0.z; Bs[0][ak + 3][am] = b0.w;
    __syncthreads();

    float acc[4][4];
    #pragma unroll
    for (int i = 0; i < 4; i++)
        #pragma unroll
        for (int j = 0; j < 4; j++) acc[i][j] = 0.f;

    const int nChunks = K >> 4;
    int buf = 0;
    for (int c = 0; c < nChunks; c++) {
        float4 aN, bN;
        const bool more = (c + 1 < nChunks);
        if (more) {
            aN = *(const float4*)(Aptr + (c + 1) * 16);
            bN = wok ? *(const float4*)(Wptr + (c + 1) * 16) : make_float4(0.f, 0.f, 0.f, 0.f);
        }
        #pragma unroll
        for (int k = 0; k < 16; k++) {
            float4 a = *(const float4*)(&As[buf][k][tr * 4]);
            float4 b = *(const float4*)(&Bs[buf][k][tc * 4]);
            acc[0][0] = fmaf(a.x, b.x, acc[0][0]); acc[0][1] = fmaf(a.x, b.y, acc[0][1]);
            acc[0][2] = fmaf(a.x, b.z, acc[0][2]); acc[0][3] = fmaf(a.x, b.w, acc[0][3]);
            acc[1][0] = fmaf(a.y, b.x, acc[1][0]); acc[1][1] = fmaf(a.y, b.y, acc[1][1]);
            acc[1][2] = fmaf(a.y, b.z, acc[1][2]); acc[1][3] = fmaf(a.y, b.w, acc[1][3]);
            acc[2][0] = fmaf(a.z, b.x, acc[2][0]); acc[2][1] = fmaf(a.z, b.y, acc[2][1]);
            acc[2][2] = fmaf(a.z, b.z, acc[2][2]); acc[2][3] = fmaf(a.z, b.w, acc[2][3]);
            acc[3][0] = fmaf(a.w, b.x, acc[3][0]); acc[3][1] = fmaf(a.w, b.y, acc[3][1]);
            acc[3][2] = fmaf(a.w, b.z, acc[3][2]); acc[3][3] = fmaf(a.w, b.w, acc[3][3]);
        }
        if (more) {
            const int nb = buf ^ 1;
            As[nb][ak + 0][am] = aN.x; As[nb][ak + 1][am] = aN.y; As[nb][ak + 2][am] = aN.z; As[nb][ak + 3][am] = aN.w;
            Bs[nb][ak + 0][am] = bN.x; Bs[nb][ak + 1][am] = bN.y; Bs[nb][ak + 2][am] = bN.z; Bs[nb][ak + 3][am] = bN.w;
            __syncthreads();
            buf = nb;
        }
    }

    #pragma unroll
    for (int i = 0; i < 4; i++) {
        const int row = rowBase + tr * 4 + i;
        #pragma unroll
        for (int j = 0; j < 4; j++) {
            const int col = colBase + tc * 4 + j;
            if (col < N) {
                float v = acc[i][j];
                if (epil != EP_NONE) v += p.bias[col];
                if (epil == EP_SILU) v = v / (1.f + __expf(-v));
                if (p.resid) v += p.resid[(size_t)row * N + col];
                p.C[(size_t)row * N + col] = v;
            }
        }
    }
}

// ---------------- depthwise causal conv (K=4) + bias + silu, both dirs ----------------
__global__ void conv_silu_kernel(const float* __restrict__ xzb, float* __restrict__ xxb,
                                 const float* __restrict__ cw0, const float* __restrict__ cb0,
                                 const float* __restrict__ cw1, const float* __restrict__ cb1)
{
    const int dir = blockIdx.y;
    const float* xz = xzb + (size_t)dir * 4194304u;
    float* out      = xxb + (size_t)dir * 2097152u;
    const float* cw = dir ? cw1 : cw0;
    const float* cb = dir ? cb1 : cb0;

    int gid = blockIdx.x * blockDim.x + threadIdx.x;   // TOK*DINNER
    int d = gid & (DINNER - 1);
    int tok = gid >> 9;
    int c = tok & (Cseq - 1);
    float w0 = cw[d * 4 + 0], w1 = cw[d * 4 + 1], w2 = cw[d * 4 + 2], w3 = cw[d * 4 + 3];
    const float* base = xz + (size_t)tok * 1024 + d;
    float v = cb[d] + w3 * base[0];
    if (c >= 1) v += w2 * base[-1024];
    if (c >= 2) v += w1 * base[-2048];
    if (c >= 3) v += w0 * base[-3072];
    out[gid] = v / (1.f + __expf(-v));
}

// ---------------- selective scan: smem-staged, fused dt-proj+softplus+z-gate ----------
// block = 256 thr = 32 channels x 8 state-pairs; grid = (16 d-chunks, 4 batch, 2 dir)
struct ScanArgs {
    const float* xz; const float* xx; const float* dbl; float* g;
    const float* A0; const float* A1; const float* D0; const float* D1;
    const float* dtw0; const float* dtw1; const float* dtb0; const float* dtb1;
};

__global__ void __launch_bounds__(256) scan_kernel(ScanArgs sa)
{
    const int dir = blockIdx.z;
    const int b   = blockIdx.y;
    const int dchunk = blockIdx.x;
    const float* xz  = sa.xz  + (size_t)dir * 4194304u;
    const float* xx  = sa.xx  + (size_t)dir * 2097152u;
    const float* dbl = sa.dbl + (size_t)dir * 196608u;
    float* g         = sa.g   + (size_t)dir * 2097152u;
    const float* A_log = dir ? sa.A1 : sa.A0;
    const float* Dp    = dir ? sa.D1 : sa.D0;
    const float* dtw   = dir ? sa.dtw1 : sa.dtw0;
    const float* dtb   = dir ? sa.dtb1 : sa.dtb0;

    const int tid = threadIdx.x;
    const int dl = tid >> 3;      // 0..31 channel within chunk
    const int o  = tid & 7;       // state-pair id (states o*2, o*2+1)
    const int d  = dchunk * 32 + dl;

    __shared__ float s_dbl[32][52];   // per-token 48 proj outputs (dt-rank|B|C)
    __shared__ float s_dtw[32][17];
    __shared__ float s_dtb[32];
    __shared__ float s_dt[32][36];
    __shared__ float s_xx[32][36];
    __shared__ float s_z [32][36];
    __shared__ float s_g [32][36];

    if (tid < 32) s_dtb[tid] = dtb[dchunk * 32 + tid];
    for (int i = tid; i < 512; i += 256)
        s_dtw[i >> 4][i & 15] = dtw[(size_t)(dchunk * 32 + (i >> 4)) * 16 + (i & 15)];

    float A0r = -expf(A_log[d * 16 + o * 2 + 0]);
    float A1r = -expf(A_log[d * 16 + o * 2 + 1]);
    float h0 = 0.f, h1 = 0.f;
    const float Dv = Dp[d];

    const size_t tokBase = (size_t)b * 1024u;

    for (int t0 = 0; t0 < 1024; t0 += 32) {
        __syncthreads();
        // stage dbl rows (48 floats each) : 384 float4
        {
            int l = tid;
            int row = l / 12, c4 = l - row * 12;
            *(float4*)&s_dbl[row][c4 * 4] =
                *(const float4*)(dbl + (tokBase + t0 + row) * 48u + c4 * 4);
            l = tid + 256;
            if (l < 384) {
                row = l / 12; c4 = l - row * 12;
                *(float4*)&s_dbl[row][c4 * 4] =
                    *(const float4*)(dbl + (tokBase + t0 + row) * 48u + c4 * 4);
            }
        }
        // stage xx and z : 256 float4 each
        {
            int row = tid >> 3, c4 = tid & 7;
            *(float4*)&s_xx[row][c4 * 4] =
                *(const float4*)(xx + (tokBase + t0 + row) * 512u + dchunk * 32 + c4 * 4);
            *(float4*)&s_z[row][c4 * 4] =
                *(const float4*)(xz + (tokBase + t0 + row) * 1024u + 512 + dchunk * 32 + c4 * 4);
        }
        __syncthreads();
        // dt = softplus(dbl[:, :16] @ dtw^T + dtb)   (32 tok x 32 ch, 4 per thread)
        #pragma unroll
        for (int i = 0; i < 4; i++) {
            int idx = tid + i * 256;
            int tt = idx >> 5, d2 = idx & 31;
            float a = s_dtb[d2];
            #pragma unroll
            for (int j = 0; j < 16; j++) a = fmaf(s_dbl[tt][j], s_dtw[d2][j], a);
            s_dt[tt][d2] = (a > 20.f) ? a : log1pf(__expf(a));
        }
        __syncthreads();
        // sequential recurrence over 32 tokens
        for (int tt = 0; tt < 32; tt++) {
            float dt = s_dt[tt][dl];
            float xv = s_xx[tt][dl];
            float dx = dt * xv;
            float dA0 = __expf(dt * A0r);
            float dA1 = __expf(dt * A1r);
            h0 = fmaf(dA0, h0, dx * s_dbl[tt][16 + o * 2 + 0]);
            h1 = fmaf(dA1, h1, dx * s_dbl[tt][16 + o * 2 + 1]);
            float y = fmaf(h0, s_dbl[tt][32 + o * 2 + 0], h1 * s_dbl[tt][32 + o * 2 + 1]);
            y += __shfl_xor_sync(0xffffffffu, y, 1);
            y += __shfl_xor_sync(0xffffffffu, y, 2);
            y += __shfl_xor_sync(0xffffffffu, y, 4);
            if (o == 0) {
                float zv = s_z[tt][dl];
                float yy = fmaf(xv, Dv, y);
                s_g[tt][dl] = yy * (zv / (1.f + __expf(-zv)));
            }
        }
        __syncthreads();
        {
            int row = tid >> 3, c4 = tid & 7;
            *(float4*)(g + (tokBase + t0 + row) * 512u + dchunk * 32 + c4 * 4) =
                *(float4*)&s_g[row][c4 * 4];
        }
    }
}

// ---------------- gate combine ----------------
__global__ void combine_kernel(const float* __restrict__ wg, const float* __restrict__ rf,
                               const float* __restrict__ rb, float* __restrict__ out)
{
    int gid = blockIdx.x * blockDim.x + threadIdx.x;   // TOK*256
    int n = gid & 255;
    int tok = gid >> 8;
    int bq = tok >> 10, c = tok & 1023;
    int rtok = (bq << 10) | (1023 - c);
    out[gid] = wg[gid] * (rf[gid] + rb[((size_t)rtok << 8) + n]);
}

// ---------------- launch ----------------
extern "C" void kernel_launch(void* const* d_in, const int* in_sizes, int n_in,
                              void* d_out, int out_size)
{
    const float* x        = (const float*)d_in[0];
    const float* W_in     = (const float*)d_in[1];
    const float* b_in     = (const float*)d_in[2];
    const float* W_wp     = (const float*)d_in[3];
    const float* b_wp     = (const float*)d_in[4];
    const float* W_fp     = (const float*)d_in[5];
    const float* b_fp     = (const float*)d_in[6];
    const float* W_bp     = (const float*)d_in[7];
    const float* b_bp     = (const float*)d_in[8];
    const float* W_out    = (const float*)d_in[9];
    const float* b_out    = (const float*)d_in[10];
    const float* norm_top = (const float*)d_in[11];

    const float* f_in_w    = (const float*)d_in[12];
    const float* f_conv_w  = (const float*)d_in[13];
    const float* f_conv_b  = (const float*)d_in[14];
    const float* f_xproj_w = (const float*)d_in[15];
    const float* f_dt_w    = (const float*)d_in[16];
    const float* f_dt_b    = (const float*)d_in[17];
    const float* f_A_log   = (const float*)d_in[18];
    const float* f_D       = (const float*)d_in[19];
    const float* f_out_w   = (const float*)d_in[20];
    const float* f_norm_w  = (const float*)d_in[21];
    const float* bk_in_w    = (const float*)d_in[22];
    const float* bk_conv_w  = (const float*)d_in[23];
    const float* bk_conv_b  = (const float*)d_in[24];
    const float* bk_xproj_w = (const float*)d_in[25];
    const float* bk_dt_w    = (const float*)d_in[26];
    const float* bk_dt_b    = (const float*)d_in[27];
    const float* bk_A_log   = (const float*)d_in[28];
    const float* bk_D       = (const float*)d_in[29];
    const float* bk_out_w   = (const float*)d_in[30];
    const float* bk_norm_w  = (const float*)d_in[31];

    float* S = nullptr;
    cudaGetSymbolAddress((void**)&S, g_scratch);

    float* xn   = S + OFF_XN;
    float* ssm  = S + OFF_SSM;
    float* wgt  = S + OFF_WG;
    float* u0   = S + OFF_U;
    float* u1   = S + OFF_U + 1048576u;
    float* xzb  = S + OFF_XZ;
    float* xxb  = S + OFF_XX;
    float* dblb = S + OFF_DBL;
    float* gb   = S + OFF_G;
    float* mob  = S + OFF_MO;
    float* res0 = S + OFF_RES;
    float* res1 = S + OFF_RES + 1048576u;
    float* comb = S + OFF_COMB;

    // top rmsnorm
    rmsnorm128_kernel<<<TOK, 128>>>(x, norm_top, xn);

    // ssm_in & silu gate (paired)
    {
        GP p0{xn, W_in, b_in, nullptr, ssm};
        GP p1{xn, W_wp, b_wp, nullptr, wgt};
        sgemm2_kernel<<<dim3(4, 64, 2), 256>>>(p0, p1, 256, 128, 128, EP_BIAS, EP_SILU, 0, 0);
    }
    // fwd/bwd projections (paired; bwd reads time-reversed rows)
    {
        GP p0{ssm, W_fp, b_fp, nullptr, u0};
        GP p1{ssm, W_bp, b_bp, nullptr, u1};
        sgemm2_kernel<<<dim3(4, 64, 2), 256>>>(p0, p1, 256, 256, 256, EP_BIAS, EP_BIAS, 0, 1);
    }
    // xz = u @ in_w^T (both dirs)
    {
        GP p0{u0, f_in_w,  nullptr, nullptr, xzb};
        GP p1{u1, bk_in_w, nullptr, nullptr, xzb + 4194304u};
        sgemm2_kernel<<<dim3(16, 64, 2), 256>>>(p0, p1, 1024, 256, 256, EP_NONE, EP_NONE, 0, 0);
    }
    // depthwise conv + silu (both dirs)
    conv_silu_kernel<<<dim3((TOK * DINNER) / 256, 2), 256>>>(xzb, xxb,
                                                             f_conv_w, f_conv_b,
                                                             bk_conv_w, bk_conv_b);
    // dbl = xx @ xproj^T (both dirs)
    {
        GP p0{xxb,            f_xproj_w,  nullptr, nullptr, dblb};
        GP p1{xxb + 2097152u, bk_xproj_w, nullptr, nullptr, dblb + 196608u};
        sgemm2_kernel<<<dim3(1, 64, 2), 256>>>(p0, p1, 48, 512, 512, EP_NONE, EP_NONE, 0, 0);
    }
    // selective scan (fused dt-proj + softplus + D-skip + z-gate), both dirs
    {
        ScanArgs sa;
        sa.xz = xzb; sa.xx = xxb; sa.dbl = dblb; sa.g = gb;
        sa.A0 = f_A_log; sa.A1 = bk_A_log; sa.D0 = f_D; sa.D1 = bk_D;
        sa.dtw0 = f_dt_w; sa.dtw1 = bk_dt_w; sa.dtb0 = f_dt_b; sa.dtb1 = bk_dt_b;
        scan_kernel<<<dim3(16, 4, 2), 256>>>(sa);
    }
    // mamba out projection (both dirs)
    {
        GP p0{gb,            f_out_w,  nullptr, nullptr, mob};
        GP p1{gb + 2097152u, bk_out_w, nullptr, nullptr, mob + 1048576u};
        sgemm2_kernel<<<dim3(4, 64, 2), 256>>>(p0, p1, 256, 512, 512, EP_NONE, EP_NONE, 0, 0);
    }
    // postnorm + residual-in-mamba (both dirs)
    rmsnorm_pair_kernel<<<dim3(TOK, 2), 256>>>(mob, f_norm_w, bk_norm_w, u0, res0);

    // comb = wgate * (res_f + time-reversed res_b)
    combine_kernel<<<(TOK * 256) / 256, 256>>>(wgt, res0, res1, comb);
    // out = comb @ W_out^T + b_out + x
    {
        GP p0{comb, W_out, b_out, x, (float*)d_out};
        sgemm2_kernel<<<dim3(2, 64, 1), 256>>>(p0, p0, 128, 256, 256, EP_BIAS, EP_BIAS, 0, 0);
    }
}